// round 5
// baseline (speedup 1.0000x reference)
#include <cuda_runtime.h>

#define NROWS 262144
#define DDIM  256
#define NCLUS 512
#define NPAIRS (NCLUS * (NCLUS - 1) / 2)   // 130816

#define CSTRIDE 32              // pad counters to 128B for L2-slice spread
#define CTAS    148             // <= SM count on B300(148)/GB300(152): co-resident
#define THREADS 512
#define SROWS   1772            // ceil(NROWS/CTAS); 148*1772 = 262256 >= NROWS
#define RPT     4               // ceil(SROWS/THREADS)
#define NTASKS  1024            // (cluster, half) center tasks
#define PCAP    640             // smem perm staging capacity per task

#define PT  32
#define DCH 64
#define NT  (NCLUS / PT)                  // 16
#define NTILES (NT * (NT + 1) / 2)        // 136

// ---------------- scratch (static __device__, zero-initialized) -------------
__device__ int      g_counts[NCLUS * CSTRIDE];  // atomic counters; reset in-kernel
__device__ int      g_perm[NROWS];
__device__ float    g_sum[NCLUS * DDIM];
__device__ float    g_accum;
__device__ unsigned g_barrier;                  // monotone grid-barrier counter

// Replay-safe monotone grid barrier: all CTAS co-resident (1 CTA/SM).
__device__ __forceinline__ void grid_bar() {
    __syncthreads();
    if (threadIdx.x == 0) {
        __threadfence();
        unsigned t = atomicAdd(&g_barrier, 1u);
        unsigned target = (t / CTAS + 1u) * CTAS;
        while ((int)(*(volatile unsigned*)&g_barrier - target) < 0) { }
        __threadfence();
    }
    __syncthreads();
}

__global__ __launch_bounds__(THREADS) void k_fused(const float* __restrict__ M,
                                                   const int* __restrict__ label,
                                                   float* __restrict__ out) {
    __shared__ int    s_cnt[NCLUS];     // local hist, then global counts
    __shared__ int    s_base[NCLUS];    // this CTA's claimed base per cluster
    __shared__ int    s_off[NCLUS];     // global exclusive offsets
    __shared__ float  s_inv[NCLUS];
    __shared__ int    s_wsum[16];
    __shared__ int    sperm[PCAP];
    __shared__ float4 sred[7][64];
    __shared__ float  Ci[PT][DCH + 1];
    __shared__ float  Cj[PT][DCH + 1];
    __shared__ float  red[16];

    const int tid = threadIdx.x;
    const int bid = blockIdx.x;
    const int base = bid * SROWS;
    const int lim  = (base + SROWS < NROWS) ? base + SROWS : NROWS;

    // ======== phase 1: local histogram + local ranks ========
    s_cnt[tid] = 0;
    __syncthreads();

    int lab[RPT], lrk[RPT];
#pragma unroll
    for (int k = 0; k < RPT; k++) {
        int i = base + k * THREADS + tid;
        if (i < lim) {
            int l = __ldg(&label[i]);
            lab[k] = l;
            lrk[k] = atomicAdd(&s_cnt[l], 1);
        } else lab[k] = -1;
    }
    __syncthreads();

    // claim global per-cluster base (one counter per thread)
    {
        int n = s_cnt[tid];
        s_base[tid] = (n > 0) ? atomicAdd(&g_counts[tid * CSTRIDE], n) : 0;
    }
    // zero g_sum (131072 floats across 148 CTAs) while atomics drain
#pragma unroll
    for (int k = 0; k < 2; k++) {
        int idx = bid * 1024 + k * THREADS + tid;
        if (idx < NCLUS * DDIM) g_sum[idx] = 0.0f;
    }
    if (bid == 0 && tid == 0) g_accum = 0.0f;

    grid_bar();   // (1) global counts final

    // ======== scan: every CTA computes offsets locally, keeps in smem ========
    const int lane = tid & 31, w = tid >> 5;
    int cnt = g_counts[tid * CSTRIDE];
    int inc = cnt;
#pragma unroll
    for (int o = 1; o < 32; o <<= 1) {
        int v = __shfl_up_sync(0xffffffffu, inc, o);
        if (lane >= o) inc += v;
    }
    if (lane == 31) s_wsum[w] = inc;
    __syncthreads();
    if (w == 0 && lane < 16) {
        int v = s_wsum[lane];
        int s = v;
#pragma unroll
        for (int o = 1; o < 16; o <<= 1) {
            int u = __shfl_up_sync(0x0000ffffu, s, o);
            if (lane >= o) s += u;
        }
        s_wsum[lane] = s - v;
    }
    __syncthreads();
    int excl = s_wsum[w] + (inc - cnt);
    s_off[tid] = excl;
    s_cnt[tid] = cnt;                         // overwrite local hist with global cnt
    s_inv[tid] = 1.0f / (float)(cnt > 0 ? cnt : 1);
    __syncthreads();

    // ======== scatter permutation (labels/ranks still in registers) ========
#pragma unroll
    for (int k = 0; k < RPT; k++) {
        int c = lab[k];
        if (c >= 0) {
            int i = base + k * THREADS + tid;
            g_perm[s_off[c] + s_base[c] + lrk[k]] = i;
        }
    }

    grid_bar();   // (2) permutation final; g_sum zeroed

    if (bid == 0) g_counts[tid * CSTRIDE] = 0;   // clean for next replay

    // ======== center phase: persistent loop over (cluster, half) tasks ========
    {
        const int grp  = tid >> 6;    // 0..7
        const int col4 = tid & 63;
        const float4* __restrict__ Mv = (const float4*)M;

        for (int task = bid; task < NTASKS; task += CTAS) {
            const int c = task >> 1, h = task & 1;
            const int start = s_off[c];
            const int ccnt  = s_cnt[c];
            const int s0 = (ccnt * h) >> 1;
            const int s1 = (ccnt * (h + 1)) >> 1;
            const int n  = s1 - s0;

            __syncthreads();   // protect sperm/sred reuse from previous task
            float4 a0 = {0,0,0,0}, a1 = {0,0,0,0}, a2 = {0,0,0,0}, a3 = {0,0,0,0};

            if (n <= PCAP) {
                for (int r = tid; r < n; r += THREADS) sperm[r] = g_perm[start + s0 + r];
                __syncthreads();
                int r = grp;
                for (; r + 24 < n; r += 32) {
                    float4 v0 = __ldcs(&Mv[(size_t)sperm[r]      * 64 + col4]);
                    float4 v1 = __ldcs(&Mv[(size_t)sperm[r + 8]  * 64 + col4]);
                    float4 v2 = __ldcs(&Mv[(size_t)sperm[r + 16] * 64 + col4]);
                    float4 v3 = __ldcs(&Mv[(size_t)sperm[r + 24] * 64 + col4]);
                    a0.x += v0.x; a0.y += v0.y; a0.z += v0.z; a0.w += v0.w;
                    a1.x += v1.x; a1.y += v1.y; a1.z += v1.z; a1.w += v1.w;
                    a2.x += v2.x; a2.y += v2.y; a2.z += v2.z; a2.w += v2.w;
                    a3.x += v3.x; a3.y += v3.y; a3.z += v3.z; a3.w += v3.w;
                }
                for (; r < n; r += 8) {
                    float4 v = __ldcs(&Mv[(size_t)sperm[r] * 64 + col4]);
                    a0.x += v.x; a0.y += v.y; a0.z += v.z; a0.w += v.w;
                }
            } else {   // fallback (statistically unreachable)
                __syncthreads();
                for (int r = grp; r < n; r += 8) {
                    float4 v = __ldcs(&Mv[(size_t)__ldg(&g_perm[start + s0 + r]) * 64 + col4]);
                    a0.x += v.x; a0.y += v.y; a0.z += v.z; a0.w += v.w;
                }
            }

            float4 acc;
            acc.x = (a0.x + a1.x) + (a2.x + a3.x);
            acc.y = (a0.y + a1.y) + (a2.y + a3.y);
            acc.z = (a0.z + a1.z) + (a2.z + a3.z);
            acc.w = (a0.w + a1.w) + (a2.w + a3.w);

            if (grp > 0) sred[grp - 1][col4] = acc;
            __syncthreads();
            if (grp == 0) {
#pragma unroll
                for (int g = 0; g < 7; g++) {
                    float4 b = sred[g][col4];
                    acc.x += b.x; acc.y += b.y; acc.z += b.z; acc.w += b.w;
                }
                float* dst = g_sum + c * DDIM + col4 * 4;
                atomicAdd(dst + 0, acc.x);
                atomicAdd(dst + 1, acc.y);
                atomicAdd(dst + 2, acc.z);
                atomicAdd(dst + 3, acc.w);
            }
        }
    }

    grid_bar();   // (3) g_sum final

    // ======== pdist phase: persistent loop over triangular tiles ========
    {
        const int ty = tid >> 4;        // 0..31: i-row in tile
        const int tx = tid & 15;        // j-col pair {2tx, 2tx+1}
        float csum = 0.0f;

        for (int tile = bid; tile < NTILES; tile += CTAS) {
            int b = tile, bi = 0, nb = NT;
            while (b >= nb) { b -= nb; bi++; nb--; }
            const int bj = bi + b;
            const int i0 = bi * PT, j0 = bj * PT;

            float s0 = 0.f, s1 = 0.f;
            for (int dbase = 0; dbase < DDIM; dbase += DCH) {
                __syncthreads();
                for (int idx = tid; idx < PT * DCH; idx += THREADS) {
                    int r = idx / DCH, col = idx % DCH;
                    Ci[r][col] = g_sum[(i0 + r) * DDIM + dbase + col] * s_inv[i0 + r];
                    Cj[r][col] = g_sum[(j0 + r) * DDIM + dbase + col] * s_inv[j0 + r];
                }
                __syncthreads();
#pragma unroll 8
                for (int d = 0; d < DCH; d++) {
                    float ia = Ci[ty][d];
                    float ja = Cj[2 * tx + 0][d];
                    float jb = Cj[2 * tx + 1][d];
                    float d0 = ia - ja; s0 += d0 * d0;
                    float d1 = ia - jb; s1 += d1 * d1;
                }
            }
            const int gi  = i0 + ty;
            const int gj0 = j0 + 2 * tx, gj1 = gj0 + 1;
            if (gj0 > gi) csum += sqrtf(fmaxf(s0, 1e-12f));
            if (gj1 > gi) csum += sqrtf(fmaxf(s1, 1e-12f));
        }

        // CTA reduction + single atomic
#pragma unroll
        for (int off = 16; off > 0; off >>= 1)
            csum += __shfl_down_sync(0xffffffffu, csum, off);
        if ((tid & 31) == 0) red[tid >> 5] = csum;
        __syncthreads();
        if (tid == 0) {
            float blk = 0.f;
#pragma unroll
            for (int i = 0; i < 16; i++) blk += red[i];
            atomicAdd(&g_accum, blk);
        }
    }

    grid_bar();   // (4) g_accum final

    if (bid == 0 && tid == 0) out[0] = -g_accum / (float)NPAIRS;
}

extern "C" void kernel_launch(void* const* d_in, const int* in_sizes, int n_in,
                              void* d_out, int out_size) {
    const float* matrix = (const float*)d_in[0];
    const int*   label  = (const int*)d_in[1];
    float* out = (float*)d_out;

    k_fused<<<CTAS, THREADS>>>(matrix, label, out);
}

// round 7
// speedup vs baseline: 1.4515x; 1.4515x over previous
#include <cuda_runtime.h>

#define NROWS 262144
#define DDIM  256
#define NCLUS 512
#define NPAIRS (NCLUS * (NCLUS - 1) / 2)   // 130816

#define CSTRIDE 32               // pad counters to 128B for L2-slice spread
#define SORT_CTAS 512            // 4 CTAs/SM on 148 SMs (592 slots): co-resident
#define SORT_THREADS 512         // 1 row per thread
#define SEGS 4
#define CENTER_CTAS (NCLUS * SEGS)         // 2048

// ---------------- scratch (static __device__, zero-initialized) -------------
__device__ int      g_counts[NCLUS * CSTRIDE];  // atomic counters; reset in k_center
__device__ int      g_cnt[NCLUS];
__device__ int      g_offsets[NCLUS];
__device__ float    g_inv[NCLUS];
__device__ int      g_perm[NROWS];
__device__ float    g_sum[NCLUS * DDIM];        // zeroed in k_sort
__device__ float    g_accum;
__device__ int      g_done;
__device__ unsigned g_barrier;                  // monotone grid-barrier counter

// Replay-safe monotone grid barrier (all SORT_CTAS co-resident).
__device__ __forceinline__ void grid_bar() {
    __syncthreads();
    if (threadIdx.x == 0) {
        __threadfence();
        unsigned t = atomicAdd(&g_barrier, 1u);
        unsigned target = (t / SORT_CTAS + 1u) * SORT_CTAS;
        while ((int)(*(volatile unsigned*)&g_barrier - target) < 0) { }
        __threadfence();
    }
    __syncthreads();
}

// ---------------- kernel 1: rank + prefix + scatter, 1 row/thread -----------
__global__ __launch_bounds__(SORT_THREADS, 4) void k_sort(const int* __restrict__ label) {
    __shared__ int s_cnt[NCLUS];    // local histogram
    __shared__ int s_base[NCLUS];   // this CTA's claimed base per cluster
    __shared__ int s_off[NCLUS];    // global exclusive offsets
    __shared__ int s_wsum[16];
    const int tid = threadIdx.x;
    const int bid = blockIdx.x;
    const int i   = bid * SORT_THREADS + tid;

    s_cnt[tid] = 0;
    __syncthreads();

    // phase 1: local histogram + local rank (single-depth chain)
    const int l  = __ldg(&label[i]);
    const int rk = atomicAdd(&s_cnt[l], 1);
    __syncthreads();

    // claim global per-cluster base
    {
        int n = s_cnt[tid];
        s_base[tid] = (n > 0) ? atomicAdd(&g_counts[tid * CSTRIDE], n) : 0;
    }
    // zero g_sum (131072 floats / 512 CTAs = 256 each) while atomics drain
    if (tid < 256) g_sum[bid * 256 + tid] = 0.0f;
    if (bid == 0 && tid == 0) g_accum = 0.0f;

    grid_bar();   // global counts final

    // warp-shuffle prefix over 512 global counts (each CTA locally)
    const int lane = tid & 31, w = tid >> 5;
    int cnt = g_counts[tid * CSTRIDE];
    int inc = cnt;
#pragma unroll
    for (int o = 1; o < 32; o <<= 1) {
        int v = __shfl_up_sync(0xffffffffu, inc, o);
        if (lane >= o) inc += v;
    }
    if (lane == 31) s_wsum[w] = inc;
    __syncthreads();
    if (w == 0 && lane < 16) {
        int v = s_wsum[lane];
        int s = v;
#pragma unroll
        for (int o = 1; o < 16; o <<= 1) {
            int u = __shfl_up_sync(0x0000ffffu, s, o);
            if (lane >= o) s += u;
        }
        s_wsum[lane] = s - v;
    }
    __syncthreads();
    int excl = s_wsum[w] + (inc - cnt);
    s_off[tid] = excl;
    if (bid == 0) {
        g_offsets[tid] = excl;
        g_cnt[tid]     = cnt;
        g_inv[tid]     = 1.0f / (float)(cnt > 0 ? cnt : 1);
    }
    __syncthreads();

    // phase 2: scatter permutation
    g_perm[s_off[l] + s_base[l] + rk] = i;
}

// ---------------- kernel 2: segmented gather-sum (HBM hot path) -------------
__global__ __launch_bounds__(256) void k_center(const float* __restrict__ M) {
    __shared__ int    sperm[1024];
    __shared__ float4 sred[3][64];
    const int c     = blockIdx.x >> 2;
    const int seg   = blockIdx.x & 3;
    const int t     = threadIdx.x;

    // reset sort counters for next graph replay (ordered by kernel boundary)
    if (t == 0 && blockIdx.x < NCLUS) g_counts[blockIdx.x * CSTRIDE] = 0;

    const int start = g_offsets[c];
    const int cnt   = g_cnt[c];
    const int s0    = (cnt * seg) >> 2;
    const int s1    = (cnt * (seg + 1)) >> 2;
    const int n     = s1 - s0;
    const int grp   = t >> 6;      // 0..3: row phase
    const int col4  = t & 63;      // float4 column

    const float4* __restrict__ Mv = (const float4*)M;
    float4 a0 = {0,0,0,0}, a1 = {0,0,0,0}, a2 = {0,0,0,0}, a3 = {0,0,0,0};

    if (n <= 1024) {
        for (int r = t; r < n; r += 256) sperm[r] = g_perm[start + s0 + r];
        __syncthreads();
        int r = grp;
        for (; r + 12 < n; r += 16) {
            float4 v0 = __ldcs(&Mv[(size_t)sperm[r]      * 64 + col4]);
            float4 v1 = __ldcs(&Mv[(size_t)sperm[r + 4]  * 64 + col4]);
            float4 v2 = __ldcs(&Mv[(size_t)sperm[r + 8]  * 64 + col4]);
            float4 v3 = __ldcs(&Mv[(size_t)sperm[r + 12] * 64 + col4]);
            a0.x += v0.x; a0.y += v0.y; a0.z += v0.z; a0.w += v0.w;
            a1.x += v1.x; a1.y += v1.y; a1.z += v1.z; a1.w += v1.w;
            a2.x += v2.x; a2.y += v2.y; a2.z += v2.z; a2.w += v2.w;
            a3.x += v3.x; a3.y += v3.y; a3.z += v3.z; a3.w += v3.w;
        }
        for (; r < n; r += 4) {
            float4 v = __ldcs(&Mv[(size_t)sperm[r] * 64 + col4]);
            a0.x += v.x; a0.y += v.y; a0.z += v.z; a0.w += v.w;
        }
    } else {  // safety fallback (statistically unreachable)
        for (int r = grp; r < n; r += 4) {
            float4 v = __ldcs(&Mv[(size_t)__ldg(&g_perm[start + s0 + r]) * 64 + col4]);
            a0.x += v.x; a0.y += v.y; a0.z += v.z; a0.w += v.w;
        }
        __syncthreads();
    }

    float4 acc;
    acc.x = (a0.x + a1.x) + (a2.x + a3.x);
    acc.y = (a0.y + a1.y) + (a2.y + a3.y);
    acc.z = (a0.z + a1.z) + (a2.z + a3.z);
    acc.w = (a0.w + a1.w) + (a2.w + a3.w);

    if (grp > 0) sred[grp - 1][col4] = acc;
    __syncthreads();
    if (grp == 0) {
        float4 b0 = sred[0][col4], b1 = sred[1][col4], b2 = sred[2][col4];
        acc.x += b0.x + b1.x + b2.x;
        acc.y += b0.y + b1.y + b2.y;
        acc.z += b0.z + b1.z + b2.z;
        acc.w += b0.w + b1.w + b2.w;
        float* dst = g_sum + c * DDIM + col4 * 4;
        atomicAdd(dst + 0, acc.x);
        atomicAdd(dst + 1, acc.y);
        atomicAdd(dst + 2, acc.z);
        atomicAdd(dst + 3, acc.w);
    }
}

// ---------------- kernel 3: tiled pdist (divide fused into load) + finalize -
#define PT 32
#define DCH 64
#define NT (NCLUS / PT)                 // 16 -> 136 blocks
#define PDIST_BLOCKS (NT * (NT + 1) / 2)
__global__ __launch_bounds__(256) void k_pdist(float* __restrict__ out) {
    __shared__ float Ci[PT][DCH + 1];
    __shared__ float Cj[PT][DCH + 1];
    __shared__ float red[8];

    int b = blockIdx.x;
    int bi = 0, nb = NT;
    while (b >= nb) { b -= nb; bi++; nb--; }
    int bj = bi + b;
    const int i0 = bi * PT, j0 = bj * PT;

    const int tid = threadIdx.x;
    const int tx = tid & 15, ty = tid >> 4;

    float s00 = 0.f, s01 = 0.f, s10 = 0.f, s11 = 0.f;

    for (int dbase = 0; dbase < DDIM; dbase += DCH) {
        for (int idx = tid; idx < PT * DCH; idx += 256) {
            int r = idx / DCH, col = idx % DCH;
            Ci[r][col] = g_sum[(i0 + r) * DDIM + dbase + col] * g_inv[i0 + r];
            Cj[r][col] = g_sum[(j0 + r) * DDIM + dbase + col] * g_inv[j0 + r];
        }
        __syncthreads();
#pragma unroll 8
        for (int d = 0; d < DCH; d++) {
            float ia = Ci[2 * ty + 0][d];
            float ib = Ci[2 * ty + 1][d];
            float ja = Cj[2 * tx + 0][d];
            float jb = Cj[2 * tx + 1][d];
            float d00 = ia - ja; s00 += d00 * d00;
            float d01 = ia - jb; s01 += d01 * d01;
            float d10 = ib - ja; s10 += d10 * d10;
            float d11 = ib - jb; s11 += d11 * d11;
        }
        __syncthreads();
    }

    float local = 0.f;
    {
        int gi0 = i0 + 2 * ty, gi1 = gi0 + 1;
        int gj0 = j0 + 2 * tx, gj1 = gj0 + 1;
        if (gj0 > gi0) local += sqrtf(fmaxf(s00, 1e-12f));
        if (gj1 > gi0) local += sqrtf(fmaxf(s01, 1e-12f));
        if (gj0 > gi1) local += sqrtf(fmaxf(s10, 1e-12f));
        if (gj1 > gi1) local += sqrtf(fmaxf(s11, 1e-12f));
    }
#pragma unroll
    for (int off = 16; off > 0; off >>= 1)
        local += __shfl_down_sync(0xffffffffu, local, off);
    if ((tid & 31) == 0) red[tid >> 5] = local;
    __syncthreads();
    if (tid == 0) {
        float blk = 0.f;
#pragma unroll
        for (int w = 0; w < 8; w++) blk += red[w];
        atomicAdd(&g_accum, blk);
        __threadfence();
        int prev = atomicAdd(&g_done, 1);
        if (prev == PDIST_BLOCKS - 1) {
            g_done = 0;
            out[0] = -g_accum / (float)NPAIRS;
        }
    }
}

extern "C" void kernel_launch(void* const* d_in, const int* in_sizes, int n_in,
                              void* d_out, int out_size) {
    const float* matrix = (const float*)d_in[0];
    const int*   label  = (const int*)d_in[1];
    float* out = (float*)d_out;

    k_sort<<<SORT_CTAS, SORT_THREADS>>>(label);
    k_center<<<CENTER_CTAS, 256>>>(matrix);
    k_pdist<<<PDIST_BLOCKS, 256>>>(out);
}